// round 7
// baseline (speedup 1.0000x reference)
#include <cuda_runtime.h>
#include <cstdint>

// QConv2d fused, 2 batches per CTA, grid 128 (one wave, 1 CTA/SM).
//   new_rho[(c,P),(c',P')] = sum_{e,e'} cc[c,e] cc[c',e'] A[(e,P),(e',P')]
//   cc[c,e]=uc[c,e+2],  A = (I2 (x) ux (x) uy) rho (same)^T  (4 separable passes).
// Each barrier-delimited phase handles both batches back-to-back: halves
// per-batch barrier overhead, doubles per-phase ILP. Epilogue reads each A
// element once and emits all 16 (c,c') blocks. f32x2 math, 128-bit smem/gmem.

#define ST 132   // A row stride: 128 + 4 pad, 16B-aligned, conflict-free
#define NT 512
#define ASZ (128 * ST)

typedef unsigned long long u64;

__device__ __forceinline__ u64 pk2(float a, float b) {
    u64 r; asm("mov.b64 %0,{%1,%2};" : "=l"(r) : "f"(a), "f"(b)); return r;
}
__device__ __forceinline__ u64 mul2(u64 a, u64 b) {
    u64 r; asm("mul.rn.f32x2 %0,%1,%2;" : "=l"(r) : "l"(a), "l"(b)); return r;
}
__device__ __forceinline__ void fma2(u64& d, u64 a, u64 b) {
    asm("fma.rn.f32x2 %0,%1,%2,%0;" : "+l"(d) : "l"(a), "l"(b));
}

extern __shared__ float smf[];

__global__ __launch_bounds__(NT, 1)
void qconv2d_kernel(const float* __restrict__ rho,
                    const float* __restrict__ ux,
                    const float* __restrict__ uy,
                    const float* __restrict__ uc,
                    float* __restrict__ out) {
    float* A0   = smf;                   // batch 0 buffer: 128*132 floats
    float* A1   = smf + ASZ;             // batch 1 buffer
    u64*   uxd  = (u64*)(smf + 2 * ASZ); // 64: (ux[k,i], ux[k,i])
    u64*   uyd  = uxd + 64;              // 64
    u64*   uypp = uyd + 64;              // 32: (uy[2kp,j], uy[2kp+1,j])
    u64*   sccd = uypp + 32;             // 8:  dup (uc[c,e+2])

    const int t  = threadIdx.x;
    const int b0 = blockIdx.x * 2;

    if (t < 64) { float vx = ux[t], vy = uy[t]; uxd[t] = pk2(vx, vx); uyd[t] = pk2(vy, vy); }
    else if (t < 96) {
        int m = t - 64, kp = m >> 3, j = m & 7;
        uypp[m] = pk2(uy[(2 * kp) * 8 + j], uy[(2 * kp + 1) * 8 + j]);
    } else if (t < 104) {
        int m = t - 96; float v = uc[(m >> 1) * 4 + 2 + (m & 1)];
        sccd[m] = pk2(v, v);
    }

    // ---- Pass 1 (rows, uy over j): GMEM -> smem, both batches (16 LDGs in flight).
    {
        int s4 = t & 31, gi = t >> 5;            // gi = (e,i) 0..15
        const float* rb0 = rho + (size_t)b0 * 16384 + 4 * s4;
        ulonglong2 in0[8], in1[8];
#pragma unroll
        for (int j = 0; j < 8; j++)
            in0[j] = *(const ulonglong2*)(rb0 + (size_t)(gi * 8 + j) * 128);
#pragma unroll
        for (int j = 0; j < 8; j++)
            in1[j] = *(const ulonglong2*)(rb0 + 16384 + (size_t)(gi * 8 + j) * 128);
        __syncthreads();                         // tables ready
#pragma unroll
        for (int k = 0; k < 8; k++) {
            u64 c0 = uyd[k * 8];
            u64 ax = mul2(c0, in0[0].x), ay = mul2(c0, in0[0].y);
#pragma unroll
            for (int j = 1; j < 8; j++) { u64 c = uyd[k * 8 + j]; fma2(ax, c, in0[j].x); fma2(ay, c, in0[j].y); }
            ulonglong2 o; o.x = ax; o.y = ay;
            *(ulonglong2*)&A0[(gi * 8 + k) * ST + 4 * s4] = o;
        }
#pragma unroll
        for (int k = 0; k < 8; k++) {
            u64 c0 = uyd[k * 8];
            u64 ax = mul2(c0, in1[0].x), ay = mul2(c0, in1[0].y);
#pragma unroll
            for (int j = 1; j < 8; j++) { u64 c = uyd[k * 8 + j]; fma2(ax, c, in1[j].x); fma2(ay, c, in1[j].y); }
            ulonglong2 o; o.x = ax; o.y = ay;
            *(ulonglong2*)&A1[(gi * 8 + k) * ST + 4 * s4] = o;
        }
    }
    __syncthreads();

    // ---- Pass 2 (rows, ux over i): rows e*64+i*8+kj -> e*64+k*8+kj, both batches.
    {
        int s4 = t & 31, rem = t >> 5;
        int kj = rem & 7, e = rem >> 3;
#pragma unroll
        for (int bb = 0; bb < 2; bb++) {
            float* A = bb ? A1 : A0;
            ulonglong2 in[8];
#pragma unroll
            for (int i = 0; i < 8; i++) in[i] = *(ulonglong2*)&A[(e * 64 + i * 8 + kj) * ST + 4 * s4];
#pragma unroll
            for (int k = 0; k < 8; k++) {
                u64 c0 = uxd[k * 8];
                u64 ax = mul2(c0, in[0].x), ay = mul2(c0, in[0].y);
#pragma unroll
                for (int i = 1; i < 8; i++) { u64 c = uxd[k * 8 + i]; fma2(ax, c, in[i].x); fma2(ay, c, in[i].y); }
                ulonglong2 o; o.x = ax; o.y = ay;
                *(ulonglong2*)&A[(e * 64 + k * 8 + kj) * ST + 4 * s4] = o;
            }
        }
    }
    __syncthreads();

    // ---- Pass 3 (cols, uy over j'): cols cg*8+j' -> cg*8+kj', paired outputs.
#pragma unroll 1
    for (int it = 0; it < 4; it++) {
        int task = t + NT * it;
        int r = task & 127, cg = task >> 7;      // cg = (e',i') 0..15
#pragma unroll
        for (int bb = 0; bb < 2; bb++) {
            float* A = bb ? A1 : A0;
            float4 p = *(float4*)&A[r * ST + cg * 8];
            float4 q = *(float4*)&A[r * ST + cg * 8 + 4];
            u64 d0 = pk2(p.x, p.x), d1 = pk2(p.y, p.y), d2 = pk2(p.z, p.z), d3 = pk2(p.w, p.w);
            u64 d4 = pk2(q.x, q.x), d5 = pk2(q.y, q.y), d6 = pk2(q.z, q.z), d7 = pk2(q.w, q.w);
            u64 o[4];
#pragma unroll
            for (int kp = 0; kp < 4; kp++) {
                u64 acc = mul2(uypp[kp * 8 + 0], d0);
                fma2(acc, uypp[kp * 8 + 1], d1); fma2(acc, uypp[kp * 8 + 2], d2);
                fma2(acc, uypp[kp * 8 + 3], d3); fma2(acc, uypp[kp * 8 + 4], d4);
                fma2(acc, uypp[kp * 8 + 5], d5); fma2(acc, uypp[kp * 8 + 6], d6);
                fma2(acc, uypp[kp * 8 + 7], d7);
                o[kp] = acc;
            }
            ulonglong2 w0, w1; w0.x = o[0]; w0.y = o[1]; w1.x = o[2]; w1.y = o[3];
            *(ulonglong2*)&A[r * ST + cg * 8] = w0;
            *(ulonglong2*)&A[r * ST + cg * 8 + 4] = w1;
        }
    }
    __syncthreads();

    // ---- Pass 4 (cols, ux over i'): cols e2*64+i*8+(4*kjq..+3), both batches.
    {
        int r = t & 127, e2 = (t >> 7) & 1, kjq = t >> 8;
        int base = r * ST + e2 * 64 + 4 * kjq;
#pragma unroll
        for (int bb = 0; bb < 2; bb++) {
            float* A = bb ? A1 : A0;
            ulonglong2 in[8];
#pragma unroll
            for (int i = 0; i < 8; i++) in[i] = *(ulonglong2*)&A[base + 8 * i];
#pragma unroll
            for (int k = 0; k < 8; k++) {
                u64 c0 = uxd[k * 8];
                u64 ax = mul2(c0, in[0].x), ay = mul2(c0, in[0].y);
#pragma unroll
                for (int i = 1; i < 8; i++) { u64 c = uxd[k * 8 + i]; fma2(ax, c, in[i].x); fma2(ay, c, in[i].y); }
                ulonglong2 o; o.x = ax; o.y = ay;
                *(ulonglong2*)&A[base + 8 * k] = o;
            }
        }
    }
    __syncthreads();

    // ---- Epilogue: each (P, col-quad) read ONCE; emit all 16 (c,cp) blocks.
#pragma unroll 1
    for (int it = 0; it < 2; it++) {
        int task = t + NT * it;
        int q = task & 15, P = task >> 4;        // q: col quad 0..15, P: 0..63
#pragma unroll
        for (int bb = 0; bb < 2; bb++) {
            float* A = bb ? A1 : A0;
            float* ob = out + (size_t)(b0 + bb) * 65536 + (size_t)P * 256 + 4 * q;
            ulonglong2 a00 = *(ulonglong2*)&A[P * ST + 4 * q];
            ulonglong2 a01 = *(ulonglong2*)&A[P * ST + 64 + 4 * q];
            ulonglong2 a10 = *(ulonglong2*)&A[(64 + P) * ST + 4 * q];
            ulonglong2 a11 = *(ulonglong2*)&A[(64 + P) * ST + 64 + 4 * q];
#pragma unroll
            for (int cp = 0; cp < 4; cp++) {
                u64 k0 = sccd[2 * cp], k1 = sccd[2 * cp + 1];
                u64 v0x = mul2(k0, a00.x); fma2(v0x, k1, a01.x);
                u64 v0y = mul2(k0, a00.y); fma2(v0y, k1, a01.y);
                u64 v1x = mul2(k0, a10.x); fma2(v1x, k1, a11.x);
                u64 v1y = mul2(k0, a10.y); fma2(v1y, k1, a11.y);
#pragma unroll
                for (int c = 0; c < 4; c++) {
                    u64 ox = mul2(sccd[2 * c], v0x); fma2(ox, sccd[2 * c + 1], v1x);
                    u64 oy = mul2(sccd[2 * c], v0y); fma2(oy, sccd[2 * c + 1], v1y);
                    ulonglong2 w; w.x = ox; w.y = oy;
                    *(ulonglong2*)(ob + (size_t)(c * 64) * 256 + cp * 64) = w;
                }
            }
        }
    }
}

extern "C" void kernel_launch(void* const* d_in, const int* in_sizes, int n_in,
                              void* d_out, int out_size) {
    const float* rho = (const float*)d_in[0];   // [256,128,128]
    const float* ux  = (const float*)d_in[1];   // [8,8]
    const float* uy  = (const float*)d_in[2];   // [8,8]
    const float* uc  = (const float*)d_in[3];   // [4,4]
    float* out = (float*)d_out;                 // [256,256,256]

    const size_t smem = (2 * ASZ) * sizeof(float)
                      + (64 + 64 + 32 + 8) * sizeof(u64);   // 136,512 B -> 1 CTA/SM
    cudaFuncSetAttribute(qconv2d_kernel,
                         cudaFuncAttributeMaxDynamicSharedMemorySize, (int)smem);
    qconv2d_kernel<<<128, NT, smem>>>(rho, ux, uy, uc, out);
}

// round 8
// speedup vs baseline: 1.1492x; 1.1492x over previous
#include <cuda_runtime.h>
#include <cstdint>

// QConv2d fused, scalar-FFMA version (f32x2 removed as pipe-saturation probe).
//   new_rho[(c,P),(c',P')] = sum_{e,e'} cc[c,e] cc[c',e'] A[(e,P),(e',P')]
//   cc[c,e]=uc[c,e+2],  A = (I2 (x) ux (x) uy) rho (same)^T  (4 separable passes).
// grid 256 (1 batch/CTA), 512 threads, pass1 reads GMEM directly, read-once
// channel-expansion epilogue with coalesced STG.128. All smem/gmem 128-bit.

#define ST 132   // A row stride: 128 + 4 pad, 16B-aligned, conflict-free
#define NT 512

__device__ __forceinline__ float4 f4fma(float c, float4 a, float4 acc) {
    acc.x = fmaf(c, a.x, acc.x); acc.y = fmaf(c, a.y, acc.y);
    acc.z = fmaf(c, a.z, acc.z); acc.w = fmaf(c, a.w, acc.w);
    return acc;
}
__device__ __forceinline__ float4 f4mul(float c, float4 a) {
    float4 r; r.x = c * a.x; r.y = c * a.y; r.z = c * a.z; r.w = c * a.w;
    return r;
}

extern __shared__ float smf[];

__global__ __launch_bounds__(NT)
void qconv2d_kernel(const float* __restrict__ rho,
                    const float* __restrict__ ux,
                    const float* __restrict__ uy,
                    const float* __restrict__ uc,
                    float* __restrict__ out) {
    float* A   = smf;                    // 128*132 floats
    float* sux = smf + 128 * ST;         // 64
    float* suy = sux + 64;               // 64
    float* scc = suy + 64;               // 8: scc[c*2+e] = uc[c, e+2]

    const int t = threadIdx.x;
    const int b = blockIdx.x;

    if (t < 64) { sux[t] = ux[t]; suy[t] = uy[t]; }
    else if (t < 72) { int m = t - 64; scc[m] = uc[(m >> 1) * 4 + 2 + (m & 1)]; }

    // ---- Pass 1 (rows, uy over j): GMEM -> smem. Task: 4 cols x (e,i) group.
    {
        int s4 = t & 31, gi = t >> 5;            // gi = (e,i) 0..15
        const float* rb = rho + (size_t)b * 16384 + 4 * s4;
        float4 in[8];
#pragma unroll
        for (int j = 0; j < 8; j++)
            in[j] = *(const float4*)(rb + (size_t)(gi * 8 + j) * 128);
        __syncthreads();                         // tables ready
#pragma unroll
        for (int k = 0; k < 8; k++) {
            float4 acc = f4mul(suy[k * 8], in[0]);
#pragma unroll
            for (int j = 1; j < 8; j++) acc = f4fma(suy[k * 8 + j], in[j], acc);
            *(float4*)&A[(gi * 8 + k) * ST + 4 * s4] = acc;
        }
    }
    __syncthreads();

    // ---- Pass 2 (rows, ux over i): rows e*64+i*8+kj -> e*64+k*8+kj.
    {
        int s4 = t & 31, rem = t >> 5;
        int kj = rem & 7, e = rem >> 3;
        float4 in[8];
#pragma unroll
        for (int i = 0; i < 8; i++)
            in[i] = *(float4*)&A[(e * 64 + i * 8 + kj) * ST + 4 * s4];
#pragma unroll
        for (int k = 0; k < 8; k++) {
            float4 acc = f4mul(sux[k * 8], in[0]);
#pragma unroll
            for (int i = 1; i < 8; i++) acc = f4fma(sux[k * 8 + i], in[i], acc);
            *(float4*)&A[(e * 64 + k * 8 + kj) * ST + 4 * s4] = acc;
        }
    }
    __syncthreads();

    // ---- Pass 3 (cols, uy over j'): cols cg*8+j' -> cg*8+kj', in place.
#pragma unroll 1
    for (int it = 0; it < 4; it++) {
        int task = t + NT * it;
        int r = task & 127, cg = task >> 7;      // cg = (e',i') 0..15
        float4 p = *(float4*)&A[r * ST + cg * 8];
        float4 q = *(float4*)&A[r * ST + cg * 8 + 4];
        float v0 = p.x, v1 = p.y, v2 = p.z, v3 = p.w;
        float v4 = q.x, v5 = q.y, v6 = q.z, v7 = q.w;
        float o[8];
#pragma unroll
        for (int k = 0; k < 8; k++) {
            float acc = suy[k * 8] * v0;
            acc = fmaf(suy[k * 8 + 1], v1, acc); acc = fmaf(suy[k * 8 + 2], v2, acc);
            acc = fmaf(suy[k * 8 + 3], v3, acc); acc = fmaf(suy[k * 8 + 4], v4, acc);
            acc = fmaf(suy[k * 8 + 5], v5, acc); acc = fmaf(suy[k * 8 + 6], v6, acc);
            acc = fmaf(suy[k * 8 + 7], v7, acc);
            o[k] = acc;
        }
        *(float4*)&A[r * ST + cg * 8]     = make_float4(o[0], o[1], o[2], o[3]);
        *(float4*)&A[r * ST + cg * 8 + 4] = make_float4(o[4], o[5], o[6], o[7]);
    }
    __syncthreads();

    // ---- Pass 4 (cols, ux over i'): cols e2*64+i*8+(4*kjq..+3), one task/thread.
    {
        int r = t & 127, e2 = (t >> 7) & 1, kjq = t >> 8;
        int base = r * ST + e2 * 64 + 4 * kjq;
        float4 in[8];
#pragma unroll
        for (int i = 0; i < 8; i++) in[i] = *(float4*)&A[base + 8 * i];
#pragma unroll
        for (int k = 0; k < 8; k++) {
            float4 acc = f4mul(sux[k * 8], in[0]);
#pragma unroll
            for (int i = 1; i < 8; i++) acc = f4fma(sux[k * 8 + i], in[i], acc);
            *(float4*)&A[base + 8 * k] = acc;
        }
    }
    __syncthreads();

    // ---- Epilogue: each (P, col-quad) read ONCE; emit all 16 (c,c') blocks.
    const float c00 = scc[0], c01 = scc[1], c10 = scc[2], c11 = scc[3];
    const float c20 = scc[4], c21 = scc[5], c30 = scc[6], c31 = scc[7];
#pragma unroll 1
    for (int it = 0; it < 2; it++) {
        int task = t + NT * it;
        int q = task & 15, P = task >> 4;        // q: col quad 0..15, P: 0..63
        float4 a00 = *(float4*)&A[P * ST + 4 * q];
        float4 a01 = *(float4*)&A[P * ST + 64 + 4 * q];
        float4 a10 = *(float4*)&A[(64 + P) * ST + 4 * q];
        float4 a11 = *(float4*)&A[(64 + P) * ST + 64 + 4 * q];
        float* ob = out + (size_t)b * 65536 + (size_t)P * 256 + 4 * q;
#pragma unroll
        for (int cp = 0; cp < 4; cp++) {
            const float k0 = scc[2 * cp], k1 = scc[2 * cp + 1];
            float4 v0 = f4fma(k1, a01, f4mul(k0, a00));
            float4 v1 = f4fma(k1, a11, f4mul(k0, a10));
            float4 w;
            w = f4fma(c01, v1, f4mul(c00, v0));
            *(float4*)(ob + (size_t)(0 * 64) * 256 + cp * 64) = w;
            w = f4fma(c11, v1, f4mul(c10, v0));
            *(float4*)(ob + (size_t)(1 * 64) * 256 + cp * 64) = w;
            w = f4fma(c21, v1, f4mul(c20, v0));
            *(float4*)(ob + (size_t)(2 * 64) * 256 + cp * 64) = w;
            w = f4fma(c31, v1, f4mul(c30, v0));
            *(float4*)(ob + (size_t)(3 * 64) * 256 + cp * 64) = w;
        }
    }
}

extern "C" void kernel_launch(void* const* d_in, const int* in_sizes, int n_in,
                              void* d_out, int out_size) {
    const float* rho = (const float*)d_in[0];   // [256,128,128]
    const float* ux  = (const float*)d_in[1];   // [8,8]
    const float* uy  = (const float*)d_in[2];   // [8,8]
    const float* uc  = (const float*)d_in[3];   // [4,4]
    float* out = (float*)d_out;                 // [256,256,256]

    const size_t smem = (128 * ST + 64 + 64 + 8) * sizeof(float);  // ~68.1 KB
    cudaFuncSetAttribute(qconv2d_kernel,
                         cudaFuncAttributeMaxDynamicSharedMemorySize, (int)smem);
    qconv2d_kernel<<<256, NT, smem>>>(rho, ux, uy, uc, out);
}

// round 9
// speedup vs baseline: 1.1594x; 1.0089x over previous
#include <cuda_runtime.h>
#include <cstdint>

// QConv2d, two balanced kernels (fixed-coalescing version of the R3 split).
//   new_rho[(c,P),(c',P')] = sum_{e,e'} cc[c,e] cc[c',e'] A[(e,P),(e',P')]
//   cc[c,e]=uc[c,e+2],  A = L rho L^T,  L = I2 (x) ux (x) uy (separable).
// K1: scratch = L rho   (per 32-column slice; GMEM coalesced both ends)
// K2: out = expand(A L^T) per 16-P-row slice; scratch read COALESCED into smem
//     (this was R3's bug: per-lane row-strided reads, 32 lines/LDG), then
//     column passes + read-once channel expansion from smem.

typedef unsigned long long u64;

__device__ float g_scratch[256 * 128 * 128];   // 16 MB intermediate

__device__ __forceinline__ float4 f4fma(float c, float4 a, float4 acc) {
    acc.x = fmaf(c, a.x, acc.x); acc.y = fmaf(c, a.y, acc.y);
    acc.z = fmaf(c, a.z, acc.z); acc.w = fmaf(c, a.w, acc.w);
    return acc;
}
__device__ __forceinline__ float4 f4mul(float c, float4 a) {
    float4 r; r.x = c * a.x; r.y = c * a.y; r.z = c * a.z; r.w = c * a.w;
    return r;
}

// ======================= K1: left transform =======================
#define ST1 36   // 32 + 4 pad (16B-aligned rows)

__global__ __launch_bounds__(128)
void qconv2d_k1(const float* __restrict__ rho,
                const float* __restrict__ ux,
                const float* __restrict__ uy) {
    __shared__ float A[128 * ST1];
    __shared__ float sux[64], suy[64];

    const int t  = threadIdx.x;
    const int b  = blockIdx.x >> 2;
    const int cb = blockIdx.x & 3;

    if (t < 64) { sux[t] = ux[t]; suy[t] = uy[t]; }

    const int cq = t & 7;        // column quad within 32-col slice
    const int gi = t >> 3;       // (e,i) group 0..15

    // Pass A: contract uy over j, input straight from GMEM (coalesced).
    const float* rb = rho + (size_t)b * 16384 + cb * 32 + 4 * cq;
    float4 in[8];
#pragma unroll
    for (int j = 0; j < 8; j++)
        in[j] = *(const float4*)(rb + (size_t)(gi * 8 + j) * 128);
    __syncthreads();             // tables ready
#pragma unroll
    for (int k = 0; k < 8; k++) {
        float4 acc = f4mul(suy[k * 8], in[0]);
#pragma unroll
        for (int j = 1; j < 8; j++) acc = f4fma(suy[k * 8 + j], in[j], acc);
        *(float4*)&A[(gi * 8 + k) * ST1 + 4 * cq] = acc;
    }
    __syncthreads();

    // Pass B: contract ux over i, write scratch (coalesced: 4 full lines/STG).
    const int kj = (t >> 3) & 7;
    const int e  = t >> 6;
    float* sb = g_scratch + (size_t)b * 16384 + cb * 32 + 4 * cq;
    float4 in2[8];
#pragma unroll
    for (int i = 0; i < 8; i++)
        in2[i] = *(float4*)&A[(e * 64 + i * 8 + kj) * ST1 + 4 * cq];
#pragma unroll
    for (int k = 0; k < 8; k++) {
        float4 acc = f4mul(sux[k * 8], in2[0]);
#pragma unroll
        for (int i = 1; i < 8; i++) acc = f4fma(sux[k * 8 + i], in2[i], acc);
        *(float4*)(sb + (size_t)(e * 64 + k * 8 + kj) * 128) = acc;
    }
}

// ============ K2: right transform + channel expansion ============
#define ST2 132  // 128 + 4 pad

__global__ __launch_bounds__(128)
void qconv2d_k2(const float* __restrict__ ux,
                const float* __restrict__ uy,
                const float* __restrict__ uc,
                float* __restrict__ out) {
    __shared__ float A[32 * ST2];
    __shared__ float sux[64], suy[64], scc[8];

    const int t  = threadIdx.x;
    const int b  = blockIdx.x >> 2;
    const int P0 = (blockIdx.x & 3) * 16;

    if (t < 64) { sux[t] = ux[t]; suy[t] = uy[t]; }
    else if (t < 72) { int m = t - 64; scc[m] = uc[(m >> 1) * 4 + 2 + (m & 1)]; }

    // ---- Load slice: local row r (0..31) -> global row (r>>4)*64 + P0 + (r&15).
    // Lane-contiguous along columns: warp = 8 rows x 64 B contiguous per row.
    {
        int r  = t >> 2;
        int q0 = t & 3;
        int gr = ((r >> 4) << 6) + P0 + (r & 15);
        const float4* src = (const float4*)(g_scratch + (size_t)b * 16384 + (size_t)gr * 128);
        float4 v[8];
#pragma unroll
        for (int k = 0; k < 8; k++) v[k] = src[q0 + 4 * k];
#pragma unroll
        for (int k = 0; k < 8; k++)
            *(float4*)&A[r * ST2 + 4 * (q0 + 4 * k)] = v[k];
    }
    __syncthreads();

    // ---- Pass 3 (cols, uy over j'): cols cg*8+j' -> cg*8+kj', in place.
    // Each task owns its 8 cells exclusively -> no intra-pass sync needed.
#pragma unroll 1
    for (int it = 0; it < 4; it++) {
        int task = t + 128 * it;
        int r = task & 31, cg = task >> 5;       // cg = (e',i') 0..15
        float4 p = *(float4*)&A[r * ST2 + cg * 8];
        float4 q = *(float4*)&A[r * ST2 + cg * 8 + 4];
        float v0 = p.x, v1 = p.y, v2 = p.z, v3 = p.w;
        float v4 = q.x, v5 = q.y, v6 = q.z, v7 = q.w;
        float o[8];
#pragma unroll
        for (int k = 0; k < 8; k++) {
            float acc = suy[k * 8] * v0;
            acc = fmaf(suy[k * 8 + 1], v1, acc); acc = fmaf(suy[k * 8 + 2], v2, acc);
            acc = fmaf(suy[k * 8 + 3], v3, acc); acc = fmaf(suy[k * 8 + 4], v4, acc);
            acc = fmaf(suy[k * 8 + 5], v5, acc); acc = fmaf(suy[k * 8 + 6], v6, acc);
            acc = fmaf(suy[k * 8 + 7], v7, acc);
            o[k] = acc;
        }
        *(float4*)&A[r * ST2 + cg * 8]     = make_float4(o[0], o[1], o[2], o[3]);
        *(float4*)&A[r * ST2 + cg * 8 + 4] = make_float4(o[4], o[5], o[6], o[7]);
    }
    __syncthreads();

    // ---- Pass 4 (cols, ux over i'): cols e2*64+i*8+(4*kjq..+3), one task/thread.
    {
        int r = t & 31, e2 = (t >> 5) & 1, kjq = t >> 6;
        int base = r * ST2 + e2 * 64 + 4 * kjq;
        float4 in[8];
#pragma unroll
        for (int i = 0; i < 8; i++) in[i] = *(float4*)&A[base + 8 * i];
#pragma unroll
        for (int k = 0; k < 8; k++) {
            float4 acc = f4mul(sux[k * 8], in[0]);
#pragma unroll
            for (int i = 1; i < 8; i++) acc = f4fma(sux[k * 8 + i], in[i], acc);
            *(float4*)&A[base + 8 * k] = acc;
        }
    }
    __syncthreads();

    // ---- Epilogue: each (p, col-quad) read ONCE; emit all 16 (c,c') blocks.
    const float c00 = scc[0], c01 = scc[1], c10 = scc[2], c11 = scc[3];
    const float c20 = scc[4], c21 = scc[5], c30 = scc[6], c31 = scc[7];
#pragma unroll 1
    for (int it = 0; it < 2; it++) {
        int task = t + 128 * it;
        int q = task & 15, p = task >> 4;        // q: col quad 0..15, p: 0..15
        float4 a00 = *(float4*)&A[p * ST2 + 4 * q];
        float4 a01 = *(float4*)&A[p * ST2 + 64 + 4 * q];
        float4 a10 = *(float4*)&A[(16 + p) * ST2 + 4 * q];
        float4 a11 = *(float4*)&A[(16 + p) * ST2 + 64 + 4 * q];
        float* ob = out + (size_t)b * 65536 + (size_t)(P0 + p) * 256 + 4 * q;
#pragma unroll
        for (int cp = 0; cp < 4; cp++) {
            const float k0 = scc[2 * cp], k1 = scc[2 * cp + 1];
            float4 v0 = f4fma(k1, a01, f4mul(k0, a00));
            float4 v1 = f4fma(k1, a11, f4mul(k0, a10));
            float4 w;
            w = f4fma(c01, v1, f4mul(c00, v0));
            *(float4*)(ob + (size_t)(0 * 64) * 256 + cp * 64) = w;
            w = f4fma(c11, v1, f4mul(c10, v0));
            *(float4*)(ob + (size_t)(1 * 64) * 256 + cp * 64) = w;
            w = f4fma(c21, v1, f4mul(c20, v0));
            *(float4*)(ob + (size_t)(2 * 64) * 256 + cp * 64) = w;
            w = f4fma(c31, v1, f4mul(c30, v0));
            *(float4*)(ob + (size_t)(3 * 64) * 256 + cp * 64) = w;
        }
    }
}

extern "C" void kernel_launch(void* const* d_in, const int* in_sizes, int n_in,
                              void* d_out, int out_size) {
    const float* rho = (const float*)d_in[0];   // [256,128,128]
    const float* ux  = (const float*)d_in[1];   // [8,8]
    const float* uy  = (const float*)d_in[2];   // [8,8]
    const float* uc  = (const float*)d_in[3];   // [4,4]
    float* out = (float*)d_out;                 // [256,256,256]

    qconv2d_k1<<<1024, 128>>>(rho, ux, uy);
    qconv2d_k2<<<1024, 128>>>(ux, uy, uc, out);
}